// round 5
// baseline (speedup 1.0000x reference)
#include <cuda_runtime.h>

#define BB   64
#define TT   128
#define HH   256
#define INN  256
#define VV   256
#define NDLY 32
#define BH   (BB*HH)

__device__ float    g_cw[NDLY*HH*INN];
__device__ float    g_xw[BB*TT*HH];
__device__ float    g_wa1[INN*HH];
__device__ float    g_weT[HH*VV];
__device__ float    g_hist[BB*NDLY*HH];
__device__ float    g_partial[NDLY*BB*HH];
__device__ unsigned g_keys[2*BB];
__device__ int      g_tau[BB], g_done[BB], g_stepsA[BB], g_curIdx[BB];

// XLA/Eigen f32 tanh approximation (emitted by XLA for tanh.f32)
__device__ __forceinline__ float xla_tanh(float x) {
    if (fabsf(x) < 0.0004f) return x;
    float cx = fminf(fmaxf(x, -7.90531110763549805f), 7.90531110763549805f);
    float x2 = cx * cx;
    float p = fmaf(x2, -2.76076847742355e-16f, 2.00018790482477e-13f);
    p = fmaf(x2, p, -8.60467152213735e-11f);
    p = fmaf(x2, p,  5.12229709037114e-08f);
    p = fmaf(x2, p,  1.48572235717979e-05f);
    p = fmaf(x2, p,  6.37261928875436e-04f);
    p = fmaf(x2, p,  4.89352455891786e-03f);
    p = cx * p;
    float q = fmaf(x2, 1.19825839466702e-06f, 1.18534705686654e-04f);
    q = fmaf(x2, q, 2.26843463243900e-03f);
    q = fmaf(x2, q, 4.89352518554385e-03f);
    return p / q;
}

__device__ __forceinline__ void tf2x32(unsigned k0, unsigned k1,
                                       unsigned x0, unsigned x1,
                                       unsigned &o0, unsigned &o1) {
    unsigned ks2 = k0 ^ k1 ^ 0x1BD11BDAu;
    x0 += k0; x1 += k1;
#define TF_R(r) { x0 += x1; x1 = (x1 << (r)) | (x1 >> (32 - (r))); x1 ^= x0; }
    TF_R(13) TF_R(15) TF_R(26) TF_R(6)
    x0 += k1;  x1 += ks2 + 1u;
    TF_R(17) TF_R(29) TF_R(16) TF_R(24)
    x0 += ks2; x1 += k0 + 2u;
    TF_R(13) TF_R(15) TF_R(26) TF_R(6)
    x0 += k0;  x1 += k1 + 3u;
    TF_R(17) TF_R(29) TF_R(16) TF_R(24)
    x0 += k1;  x1 += ks2 + 4u;
    TF_R(13) TF_R(15) TF_R(26) TF_R(6)
    x0 += ks2; x1 += k0 + 5u;
#undef TF_R
    o0 = x0; o1 = x1;
}

__global__ void init_state_kernel() {
    int i = blockIdx.x * blockDim.x + threadIdx.x;
    if (i < BB * NDLY * HH) g_hist[i] = 0.0f;
    if (i < BB) { g_tau[i] = 0; g_done[i] = 0; g_stepsA[i] = 0; g_curIdx[i] = -1; }
}

// jax.random.split(key(42), 64), partitionable (fold-like):
//   child_b = full cipher output of cipher(key, (0, b))
__global__ void keys_kernel() {
    int tid = threadIdx.x;
    if (tid < BB) {
        unsigned o0, o1;
        tf2x32(0u, 42u, 0u, (unsigned)tid, o0, o1);
        g_keys[2 * tid]     = o0;
        g_keys[2 * tid + 1] = o1;
    }
}

// cw[dd][h][i] = relu(inv - |((dd+1)-clip(tau,1,32))*inv^2|) * lateral[h][i]
__global__ void build_cw_kernel(const float* __restrict__ lateral,
                                const float* __restrict__ tau) {
    int i = blockIdx.x * 256 + threadIdx.x;
    int dd = i >> 16;
    int hi = i & 65535;
    const float INV = 0.0625f, INV2 = 0.0625f * 0.0625f;
    float tc = fminf(fmaxf(tau[hi], 1.0f), 32.0f);
    float t1 = ((float)(dd + 1) - tc) * INV2;
    float c  = fmaxf(0.0f, INV - fabsf(t1));
    g_cw[i] = c * lateral[hi];
}

__global__ void build_aux_kernel(const float* __restrict__ w_aff,
                                 const float* __restrict__ b_aff,
                                 const float* __restrict__ w_eff) {
    int i = blockIdx.x * 256 + threadIdx.x;
    int a = i / HH, h2 = i % HH;
    g_wa1[i] = w_aff[h2 * INN + a] + b_aff[h2];
    int hh = i / VV, v = i % VV;
    g_weT[i] = w_eff[v * HH + hh];
}

// xw[m][h] = sum_i x[m][i]*w_aff[h][i] + b_aff[h],  m = b*T+t
__global__ __launch_bounds__(256) void xw_gemm_kernel(
        const float* __restrict__ x, const float* __restrict__ w_aff,
        const float* __restrict__ b_aff) {
    __shared__ float As[32][65], Ws[32][65];
    int m0 = blockIdx.x * 64, h0 = blockIdx.y * 64;
    int tid = threadIdx.x, tx = tid % 16, ty = tid / 16;
    float acc[4][4] = {{0}};
    for (int k0 = 0; k0 < INN; k0 += 32) {
        int r = tid >> 2, kq = tid & 3;
#pragma unroll
        for (int j = 0; j < 8; j++) {
            As[kq * 8 + j][r] = x[(size_t)(m0 + r) * INN + k0 + kq * 8 + j];
            Ws[kq * 8 + j][r] = w_aff[(h0 + r) * INN + k0 + kq * 8 + j];
        }
        __syncthreads();
#pragma unroll
        for (int k = 0; k < 32; k++) {
            float av[4], bv[4];
#pragma unroll
            for (int u = 0; u < 4; u++) av[u] = As[k][ty * 4 + u];
#pragma unroll
            for (int v = 0; v < 4; v++) bv[v] = Ws[k][tx * 4 + v];
#pragma unroll
            for (int u = 0; u < 4; u++)
#pragma unroll
                for (int v = 0; v < 4; v++)
                    acc[u][v] = fmaf(av[u], bv[v], acc[u][v]);
        }
        __syncthreads();
    }
#pragma unroll
    for (int u = 0; u < 4; u++)
#pragma unroll
        for (int v = 0; v < 4; v++) {
            int m = m0 + ty * 4 + u, h = h0 + tx * 4 + v;
            g_xw[(size_t)m * HH + h] = acc[u][v] + b_aff[h];
        }
}

// K1: partial[dd][b][h] = sum_i cw[dd][h][i] * hist[b][(tau_b-(dd+1))&31][i]
__global__ __launch_bounds__(256) void step_gemm_kernel() {
    __shared__ float As[32][65], Bs[32][65];
    __shared__ int rowOff[BB];
    int dd = blockIdx.y;
    int h0 = blockIdx.x * 64;
    int tid = threadIdx.x, tx = tid % 16, ty = tid / 16;
    if (tid < BB) {
        int s = (g_tau[tid] - (dd + 1)) & 31;
        rowOff[tid] = tid * (NDLY * HH) + s * HH;
    }
    __syncthreads();
    const float* cwd = g_cw + (size_t)dd * HH * INN;
    float acc[4][4] = {{0}};
    for (int k0 = 0; k0 < INN; k0 += 32) {
        int r = tid >> 2, kq = tid & 3;
#pragma unroll
        for (int j = 0; j < 8; j++) {
            As[kq * 8 + j][r] = cwd[(h0 + r) * INN + k0 + kq * 8 + j];
            Bs[kq * 8 + j][r] = g_hist[rowOff[r] + k0 + kq * 8 + j];
        }
        __syncthreads();
#pragma unroll
        for (int k = 0; k < 32; k++) {
            float av[4], bv[4];
#pragma unroll
            for (int u = 0; u < 4; u++) av[u] = As[k][ty * 4 + u];
#pragma unroll
            for (int v = 0; v < 4; v++) bv[v] = Bs[k][tx * 4 + v];
#pragma unroll
            for (int u = 0; u < 4; u++)
#pragma unroll
                for (int v = 0; v < 4; v++)
                    acc[u][v] = fmaf(av[u], bv[v], acc[u][v]);
        }
        __syncthreads();
    }
    float* P = g_partial + (size_t)dd * BH;
#pragma unroll
    for (int u = 0; u < 4; u++)
#pragma unroll
        for (int v = 0; v < 4; v++)
            P[(tx * 4 + v) * HH + h0 + ty * 4 + u] = acc[u][v];
}

// K2 (encoder)
__global__ void enc_step_kernel(int t, const int* __restrict__ lengths) {
    int b = blockIdx.x, h = threadIdx.x;
    float acc = 0.0f;
    for (int dd = NDLY - 1; dd >= 0; --dd)      // oldest delay first (chronological)
        acc += g_partial[(size_t)dd * BH + b * HH + h];
    float hv = xla_tanh(g_xw[(size_t)(b * TT + t) * HH + h] + acc);
    if (t < lengths[b]) {
        g_hist[b * (NDLY * HH) + (t & 31) * HH + h] = hv;
        if (h == 0) g_tau[b] = t + 1;
    }
}

// K2 (think/decode)
__global__ void dec_step_kernel(int g, int N,
                                const int* __restrict__ lengths,
                                const float* __restrict__ b_eff,
                                float* __restrict__ out, int writeSteps) {
    __shared__ float sh_hdel[HH];
    __shared__ float sval[VV];
    __shared__ int   sidx[VV];
    int b = blockIdx.x, tid = threadIdx.x;

    int ci = g_curIdx[b], myTau = g_tau[b], myDone = g_done[b];
    int mySteps = g_stepsA[b];
    int Lb = lengths[b];

    float acc = 0.0f;
    for (int dd = NDLY - 1; dd >= 0; --dd)
        acc += g_partial[(size_t)dd * BH + b * HH + tid];
    sh_hdel[tid] = acc;
    __syncthreads();

    // y = w_eff @ h_del + b_eff
    float y = 0.0f;
#pragma unroll 8
    for (int h = 0; h < HH; h++)
        y = fmaf(g_weT[h * VV + tid], sh_hdel[h], y);
    y = y + b_eff[tid];

    // partitionable random_bits, 32-bit: bits[i] = o0 ^ o1 of cipher(fkey, (0, i))
    unsigned kv = (g < 9) ? (unsigned)g : (unsigned)(1000 + (g - 9));
    unsigned f0, f1;
    tf2x32(g_keys[2 * b], g_keys[2 * b + 1], 0u, kv, f0, f1);
    unsigned o0, o1;
    tf2x32(f0, f1, 0u, (unsigned)tid, o0, o1);
    unsigned bits = o0 ^ o1;

    const float TINY = 1.17549435e-38f;
    float fm = __uint_as_float((bits >> 9) | 0x3F800000u) - 1.0f;
    float u  = fmaxf(TINY, fm * (1.0f - TINY) + TINY);
    float gum = -logf(-logf(u));

    sval[tid] = y + gum; sidx[tid] = tid;
    __syncthreads();
    for (int off = 128; off > 0; off >>= 1) {
        if (tid < off) {
            float v2 = sval[tid + off]; int i2 = sidx[tid + off];
            if (v2 > sval[tid] || (v2 == sval[tid] && i2 < sidx[tid])) {
                sval[tid] = v2; sidx[tid] = i2;
            }
        }
        __syncthreads();
    }
    int amax = sidx[0];

    float xin = (ci < 0) ? g_xw[(size_t)(b * TT + (Lb - 1)) * HH + tid]
                         : g_wa1[ci * HH + tid];
    float hv = xla_tanh(xin + sh_hdel[tid]);

    bool thinkPh = (g < 9);
    bool adv = thinkPh ? (myDone == 0) : true;
    if (adv) g_hist[b * (NDLY * HH) + (myTau & 31) * HH + tid] = hv;

    if (!thinkPh) {
        int k = g - 9;
        if (tid < VV - 1)
            out[((size_t)b * N + k) * (VV - 1) + tid] = y;
    }
    if (tid == 0) {
        if (thinkPh) {
            int nst = mySteps + (myDone ? 0 : 1);
            int nd = (myDone || amax == (VV - 1) || nst > 8) ? 1 : 0;
            g_stepsA[b] = nst; g_done[b] = nd;
            if (!myDone) { g_tau[b] = myTau + 1; g_curIdx[b] = amax; }
            if (g == 8 && writeSteps)
                out[(size_t)BB * N * (VV - 1) + b] = (float)nst;
        } else {
            g_tau[b] = myTau + 1; g_curIdx[b] = amax;
        }
    }
}

extern "C" void kernel_launch(void* const* d_in, const int* in_sizes, int n_in,
                              void* d_out, int out_size) {
    const float* x       = (const float*)d_in[0];
    const float* w_aff   = (const float*)d_in[1];
    const float* b_aff   = (const float*)d_in[2];
    const float* lateral = (const float*)d_in[3];
    const float* tau     = (const float*)d_in[4];
    const float* w_eff   = (const float*)d_in[5];
    const float* b_eff   = (const float*)d_in[6];
    const int*   lengths = (const int*)d_in[7];
    (void)n_in; (void)in_sizes;
    float* out = (float*)d_out;

    int Vm1 = VV - 1;
    int N, writeSteps;
    if (out_size % (BB * Vm1) == 0) { N = out_size / (BB * Vm1); writeSteps = 0; }
    else { N = (out_size - BB) / (BB * Vm1); writeSteps = 1; }

    init_state_kernel<<<(BB * NDLY * HH + 255) / 256, 256>>>();
    keys_kernel<<<1, 64>>>();
    build_cw_kernel<<<(NDLY * HH * INN) / 256, 256>>>(lateral, tau);
    build_aux_kernel<<<(INN * HH) / 256, 256>>>(w_aff, b_aff, w_eff);
    xw_gemm_kernel<<<dim3((BB * TT) / 64, HH / 64), 256>>>(x, w_aff, b_aff);

    for (int t = 0; t < TT; t++) {
        step_gemm_kernel<<<dim3(HH / 64, NDLY), 256>>>();
        enc_step_kernel<<<BB, HH>>>(t, lengths);
    }
    int G = 9 + N;
    for (int g = 0; g < G; g++) {
        step_gemm_kernel<<<dim3(HH / 64, NDLY), 256>>>();
        dec_step_kernel<<<BB, HH>>>(g, N, lengths, b_eff, out, writeSteps);
    }
}

// round 6
// speedup vs baseline: 1.0204x; 1.0204x over previous
#include <cuda_runtime.h>

#define BB   64
#define TT   128
#define HH   256
#define INN  256
#define VV   256
#define NDLY 32
#define BH   (BB*HH)
#define NSLICE (2*NDLY)   // k-split 2 per delay

__device__ float    g_cw[NDLY*HH*INN];
__device__ float    g_xw[BB*TT*HH];
__device__ float    g_wa1[INN*HH];
__device__ float    g_hist[BB*NDLY*HH];
__device__ float    g_partial[NSLICE*BB*HH];
__device__ unsigned g_keys[2*BB];
__device__ int      g_tau[BB], g_done[BB], g_stepsA[BB], g_curIdx[BB];

// ---- packed f32x2 helpers (sm_103a FFMA2 only reachable via PTX) ----------
__device__ __forceinline__ unsigned long long pkf2(float lo, float hi) {
    unsigned long long r;
    asm("mov.b64 %0, {%1, %2};" : "=l"(r) : "f"(lo), "f"(hi));
    return r;
}
__device__ __forceinline__ float2 upkf2(unsigned long long v) {
    float2 r;
    asm("mov.b64 {%0, %1}, %2;" : "=f"(r.x), "=f"(r.y) : "l"(v));
    return r;
}
__device__ __forceinline__ unsigned long long ffma2(unsigned long long a,
                                                    unsigned long long b,
                                                    unsigned long long c) {
    unsigned long long d;
    asm("fma.rn.f32x2 %0, %1, %2, %3;" : "=l"(d) : "l"(a), "l"(b), "l"(c));
    return d;
}

// XLA/Eigen f32 tanh approximation
__device__ __forceinline__ float xla_tanh(float x) {
    if (fabsf(x) < 0.0004f) return x;
    float cx = fminf(fmaxf(x, -7.90531110763549805f), 7.90531110763549805f);
    float x2 = cx * cx;
    float p = fmaf(x2, -2.76076847742355e-16f, 2.00018790482477e-13f);
    p = fmaf(x2, p, -8.60467152213735e-11f);
    p = fmaf(x2, p,  5.12229709037114e-08f);
    p = fmaf(x2, p,  1.48572235717979e-05f);
    p = fmaf(x2, p,  6.37261928875436e-04f);
    p = fmaf(x2, p,  4.89352455891786e-03f);
    p = cx * p;
    float q = fmaf(x2, 1.19825839466702e-06f, 1.18534705686654e-04f);
    q = fmaf(x2, q, 2.26843463243900e-03f);
    q = fmaf(x2, q, 4.89352518554385e-03f);
    return p / q;
}

__device__ __forceinline__ void tf2x32(unsigned k0, unsigned k1,
                                       unsigned x0, unsigned x1,
                                       unsigned &o0, unsigned &o1) {
    unsigned ks2 = k0 ^ k1 ^ 0x1BD11BDAu;
    x0 += k0; x1 += k1;
#define TF_R(r) { x0 += x1; x1 = (x1 << (r)) | (x1 >> (32 - (r))); x1 ^= x0; }
    TF_R(13) TF_R(15) TF_R(26) TF_R(6)
    x0 += k1;  x1 += ks2 + 1u;
    TF_R(17) TF_R(29) TF_R(16) TF_R(24)
    x0 += ks2; x1 += k0 + 2u;
    TF_R(13) TF_R(15) TF_R(26) TF_R(6)
    x0 += k0;  x1 += k1 + 3u;
    TF_R(17) TF_R(29) TF_R(16) TF_R(24)
    x0 += k1;  x1 += ks2 + 4u;
    TF_R(13) TF_R(15) TF_R(26) TF_R(6)
    x0 += ks2; x1 += k0 + 5u;
#undef TF_R
    o0 = x0; o1 = x1;
}

__global__ void init_state_kernel() {
    int i = blockIdx.x * blockDim.x + threadIdx.x;
    if (i < BB * NDLY * HH) g_hist[i] = 0.0f;
    if (i < BB) { g_tau[i] = 0; g_done[i] = 0; g_stepsA[i] = 0; g_curIdx[i] = -1; }
}

// split(key(42), 64), partitionable: child_b = cipher(key, (0, b))
__global__ void keys_kernel() {
    int tid = threadIdx.x;
    if (tid < BB) {
        unsigned o0, o1;
        tf2x32(0u, 42u, 0u, (unsigned)tid, o0, o1);
        g_keys[2 * tid]     = o0;
        g_keys[2 * tid + 1] = o1;
    }
}

__global__ void build_cw_kernel(const float* __restrict__ lateral,
                                const float* __restrict__ tau) {
    int i = blockIdx.x * 256 + threadIdx.x;
    int dd = i >> 16;
    int hi = i & 65535;
    const float INV = 0.0625f, INV2 = 0.0625f * 0.0625f;
    float tc = fminf(fmaxf(tau[hi], 1.0f), 32.0f);
    float t1 = ((float)(dd + 1) - tc) * INV2;
    float c  = fmaxf(0.0f, INV - fabsf(t1));
    g_cw[i] = c * lateral[hi];
}

__global__ void build_aux_kernel(const float* __restrict__ w_aff,
                                 const float* __restrict__ b_aff) {
    int i = blockIdx.x * 256 + threadIdx.x;
    int a = i / HH, h2 = i % HH;
    g_wa1[i] = w_aff[h2 * INN + a] + b_aff[h2];
}

// xw[m][h] = sum_i x[m][i]*w_aff[h][i] + b_aff[h],  m = b*T+t
__global__ __launch_bounds__(256) void xw_gemm_kernel(
        const float* __restrict__ x, const float* __restrict__ w_aff,
        const float* __restrict__ b_aff) {
    __shared__ float As[32][65], Ws[32][65];
    int m0 = blockIdx.x * 64, h0 = blockIdx.y * 64;
    int tid = threadIdx.x, tx = tid % 16, ty = tid / 16;
    float acc[4][4] = {{0}};
    for (int k0 = 0; k0 < INN; k0 += 32) {
        int r = tid >> 2, kq = tid & 3;
#pragma unroll
        for (int j = 0; j < 8; j++) {
            As[kq * 8 + j][r] = x[(size_t)(m0 + r) * INN + k0 + kq * 8 + j];
            Ws[kq * 8 + j][r] = w_aff[(h0 + r) * INN + k0 + kq * 8 + j];
        }
        __syncthreads();
#pragma unroll
        for (int k = 0; k < 32; k++) {
            float av[4], bv[4];
#pragma unroll
            for (int u = 0; u < 4; u++) av[u] = As[k][ty * 4 + u];
#pragma unroll
            for (int v = 0; v < 4; v++) bv[v] = Ws[k][tx * 4 + v];
#pragma unroll
            for (int u = 0; u < 4; u++)
#pragma unroll
                for (int v = 0; v < 4; v++)
                    acc[u][v] = fmaf(av[u], bv[v], acc[u][v]);
        }
        __syncthreads();
    }
#pragma unroll
    for (int u = 0; u < 4; u++)
#pragma unroll
        for (int v = 0; v < 4; v++) {
            int m = m0 + ty * 4 + u, h = h0 + tx * 4 + v;
            g_xw[(size_t)m * HH + h] = acc[u][v] + b_aff[h];
        }
}

// K1: partial[dd*2+kh][b][h] = sum_{i in half kh} cw[dd][h][i] * hist[b][slot(dd)][i]
// f32x2 packed inner loop; A duplicated in smem (LDS.64 broadcast), B natural pairs.
__global__ __launch_bounds__(256) void step_gemm_kernel() {
    __shared__ __align__(16) unsigned long long Asd[32][67]; // dup {a,a}
    __shared__ __align__(16) float Bs[32][66];
    __shared__ int rowOff[BB];
    int dd = blockIdx.y >> 1;
    int kh = blockIdx.y & 1;
    int h0 = blockIdx.x * 64;
    int tid = threadIdx.x, tx = tid & 15, ty = tid >> 4;
    if (tid < BB) {
        int s = (g_tau[tid] - (dd + 1)) & 31;
        rowOff[tid] = tid * (NDLY * HH) + s * HH;
    }
    __syncthreads();
    const float* cwd = g_cw + (size_t)dd * HH * INN;
    int r = tid >> 2, kq = tid & 3;
    int gb = kh * 128;
    unsigned long long acc[4][2];
#pragma unroll
    for (int u = 0; u < 4; u++) { acc[u][0] = 0ull; acc[u][1] = 0ull; }

    int brow = rowOff[r];
    for (int k0 = 0; k0 < 128; k0 += 32) {
        const float4* ap = (const float4*)(cwd + (size_t)(h0 + r) * INN + gb + k0 + kq * 8);
        float4 a0 = ap[0], a1 = ap[1];
        const float4* bp = (const float4*)(g_hist + brow + gb + k0 + kq * 8);
        float4 b0 = bp[0], b1 = bp[1];
        if (k0) __syncthreads();
        float av[8] = {a0.x, a0.y, a0.z, a0.w, a1.x, a1.y, a1.z, a1.w};
        float bv[8] = {b0.x, b0.y, b0.z, b0.w, b1.x, b1.y, b1.z, b1.w};
#pragma unroll
        for (int j = 0; j < 8; j++) {
            Asd[kq * 8 + j][r] = pkf2(av[j], av[j]);
            Bs[kq * 8 + j][r] = bv[j];
        }
        __syncthreads();
#pragma unroll
        for (int k = 0; k < 32; k++) {
            unsigned long long a0p = Asd[k][ty * 4 + 0];
            unsigned long long a1p = Asd[k][ty * 4 + 1];
            unsigned long long a2p = Asd[k][ty * 4 + 2];
            unsigned long long a3p = Asd[k][ty * 4 + 3];
            const unsigned long long* bp2 = (const unsigned long long*)&Bs[k][0];
            unsigned long long bb0 = bp2[tx * 2 + 0];
            unsigned long long bb1 = bp2[tx * 2 + 1];
            acc[0][0] = ffma2(a0p, bb0, acc[0][0]);
            acc[1][0] = ffma2(a1p, bb0, acc[1][0]);
            acc[2][0] = ffma2(a2p, bb0, acc[2][0]);
            acc[3][0] = ffma2(a3p, bb0, acc[3][0]);
            acc[0][1] = ffma2(a0p, bb1, acc[0][1]);
            acc[1][1] = ffma2(a1p, bb1, acc[1][1]);
            acc[2][1] = ffma2(a2p, bb1, acc[2][1]);
            acc[3][1] = ffma2(a3p, bb1, acc[3][1]);
        }
    }
    float* P = g_partial + (size_t)(dd * 2 + kh) * BH;
#pragma unroll
    for (int u = 0; u < 4; u++)
#pragma unroll
        for (int v2 = 0; v2 < 2; v2++) {
            float2 val = upkf2(acc[u][v2]);
            int bcol = tx * 4 + v2 * 2;
            P[(bcol + 0) * HH + h0 + ty * 4 + u] = val.x;
            P[(bcol + 1) * HH + h0 + ty * 4 + u] = val.y;
        }
}

// K2 (encoder)
__global__ void enc_step_kernel(int t, const int* __restrict__ lengths) {
    int b = blockIdx.x, h = threadIdx.x;
    float acc = 0.0f;
    for (int s = NSLICE - 1; s >= 0; --s)
        acc += g_partial[(size_t)s * BH + b * HH + h];
    float hv = xla_tanh(g_xw[(size_t)(b * TT + t) * HH + h] + acc);
    if (t < lengths[b]) {
        g_hist[b * (NDLY * HH) + (t & 31) * HH + h] = hv;
        if (h == 0) g_tau[b] = t + 1;
    }
}

// K2 (think/decode)
__global__ void dec_step_kernel(int g, int N,
                                const int* __restrict__ lengths,
                                const float* __restrict__ w_eff,
                                const float* __restrict__ b_eff,
                                float* __restrict__ out, int writeSteps) {
    __shared__ __align__(16) float sh_hdel[HH];
    __shared__ float sval[VV];
    __shared__ int   sidx[VV];
    int b = blockIdx.x, tid = threadIdx.x;

    int ci = g_curIdx[b], myTau = g_tau[b], myDone = g_done[b];
    int mySteps = g_stepsA[b];
    int Lb = lengths[b];

    float acc = 0.0f;
    for (int s = NSLICE - 1; s >= 0; --s)
        acc += g_partial[(size_t)s * BH + b * HH + tid];
    sh_hdel[tid] = acc;
    __syncthreads();

    // y = w_eff @ h_del + b_eff  (w_eff row-major (V,H): row tid contiguous)
    const unsigned long long* wrow =
        (const unsigned long long*)(w_eff + (size_t)tid * HH);
    const unsigned long long* hdl = (const unsigned long long*)sh_hdel;
    unsigned long long y2 = 0ull;
#pragma unroll 16
    for (int h2 = 0; h2 < HH / 2; h2++)
        y2 = ffma2(wrow[h2], hdl[h2], y2);
    float2 yp = upkf2(y2);
    float y = yp.x + yp.y + b_eff[tid];

    // partitionable random_bits: bits[i] = o0 ^ o1 of cipher(fold_in(key_b,kv),(0,i))
    unsigned kv = (g < 9) ? (unsigned)g : (unsigned)(1000 + (g - 9));
    unsigned f0, f1;
    tf2x32(g_keys[2 * b], g_keys[2 * b + 1], 0u, kv, f0, f1);
    unsigned o0, o1;
    tf2x32(f0, f1, 0u, (unsigned)tid, o0, o1);
    unsigned bits = o0 ^ o1;

    const float TINY = 1.17549435e-38f;
    float fm = __uint_as_float((bits >> 9) | 0x3F800000u) - 1.0f;
    float u  = fmaxf(TINY, fm * (1.0f - TINY) + TINY);
    float gum = -logf(-logf(u));

    sval[tid] = y + gum; sidx[tid] = tid;
    __syncthreads();
    for (int off = 128; off > 0; off >>= 1) {
        if (tid < off) {
            float v2 = sval[tid + off]; int i2 = sidx[tid + off];
            if (v2 > sval[tid] || (v2 == sval[tid] && i2 < sidx[tid])) {
                sval[tid] = v2; sidx[tid] = i2;
            }
        }
        __syncthreads();
    }
    int amax = sidx[0];

    float xin = (ci < 0) ? g_xw[(size_t)(b * TT + (Lb - 1)) * HH + tid]
                         : g_wa1[ci * HH + tid];
    float hv = xla_tanh(xin + sh_hdel[tid]);

    bool thinkPh = (g < 9);
    bool adv = thinkPh ? (myDone == 0) : true;
    if (adv) g_hist[b * (NDLY * HH) + (myTau & 31) * HH + tid] = hv;

    if (!thinkPh) {
        int k = g - 9;
        if (tid < VV - 1)
            out[((size_t)b * N + k) * (VV - 1) + tid] = y;
    }
    if (tid == 0) {
        if (thinkPh) {
            int nst = mySteps + (myDone ? 0 : 1);
            int nd = (myDone || amax == (VV - 1) || nst > 8) ? 1 : 0;
            g_stepsA[b] = nst; g_done[b] = nd;
            if (!myDone) { g_tau[b] = myTau + 1; g_curIdx[b] = amax; }
            if (g == 8 && writeSteps)
                out[(size_t)BB * N * (VV - 1) + b] = (float)nst;
        } else {
            g_tau[b] = myTau + 1; g_curIdx[b] = amax;
        }
    }
}

extern "C" void kernel_launch(void* const* d_in, const int* in_sizes, int n_in,
                              void* d_out, int out_size) {
    const float* x       = (const float*)d_in[0];
    const float* w_aff   = (const float*)d_in[1];
    const float* b_aff   = (const float*)d_in[2];
    const float* lateral = (const float*)d_in[3];
    const float* tau     = (const float*)d_in[4];
    const float* w_eff   = (const float*)d_in[5];
    const float* b_eff   = (const float*)d_in[6];
    const int*   lengths = (const int*)d_in[7];
    (void)n_in; (void)in_sizes;
    float* out = (float*)d_out;

    int Vm1 = VV - 1;
    int N, writeSteps;
    if (out_size % (BB * Vm1) == 0) { N = out_size / (BB * Vm1); writeSteps = 0; }
    else { N = (out_size - BB) / (BB * Vm1); writeSteps = 1; }

    init_state_kernel<<<(BB * NDLY * HH + 255) / 256, 256>>>();
    keys_kernel<<<1, 64>>>();
    build_cw_kernel<<<(NDLY * HH * INN) / 256, 256>>>(lateral, tau);
    build_aux_kernel<<<(INN * HH) / 256, 256>>>(w_aff, b_aff);
    xw_gemm_kernel<<<dim3((BB * TT) / 64, HH / 64), 256>>>(x, w_aff, b_aff);

    for (int t = 0; t < TT; t++) {
        step_gemm_kernel<<<dim3(HH / 64, NSLICE), 256>>>();
        enc_step_kernel<<<BB, HH>>>(t, lengths);
    }
    int G = 9 + N;
    for (int g = 0; g < G; g++) {
        step_gemm_kernel<<<dim3(HH / 64, NSLICE), 256>>>();
        dec_step_kernel<<<BB, HH>>>(g, N, lengths, w_eff, b_eff, out, writeSteps);
    }
}